// round 8
// baseline (speedup 1.0000x reference)
#include <cuda_runtime.h>
#include <cuda_fp16.h>
#include <cuda_bf16.h>
#include <cstdint>
#include <cstddef>

#define M_DIM 16384
#define K_DIM 4096
#define N_DIM 4096

#define BM 128
#define BN 128
#define BK 64
#define KITERS (K_DIM / BK)   // 64
#define NSTAGES 4

// smem tile rows padded to 80 B: 16B-aligned, and (20*row + k) mod 32 is a
// permutation over each fragment's warp access -> conflict-free LDS.32
#define ROW_PITCH 80
#define A_BYTES (BM * ROW_PITCH)                 // 10240
#define B_BYTES (BN * ROW_PITCH)                 // 10240
#define STAGE_BYTES (A_BYTES + B_BYTES)          // 20480
#define GEMM_SMEM (NSTAGES * STAGE_BYTES)        // 81920

static_assert(M_DIM % BM == 0 && N_DIM % BN == 0 && K_DIM % BK == 0, "tiling");

// Scratch (allocation-free rule: __device__ globals)
__device__ int8_t g_xq[(size_t)M_DIM * K_DIM];   // 64 MB
__device__ int8_t g_wq[(size_t)N_DIM * K_DIM];   // 16 MB
__device__ float  g_xs[M_DIM];
__device__ float  g_ws[N_DIM];
__device__ int    g_dtype;                        // 0=f16, 1=bf16, 2=f32

// ---------------- PTX helpers ----------------
__device__ __forceinline__ uint32_t smem_u32(const void* p) {
    uint32_t a;
    asm("{ .reg .u64 t; cvta.to.shared.u64 t, %1; cvt.u32.u64 %0, t; }" : "=r"(a) : "l"(p));
    return a;
}
__device__ __forceinline__ void cp16(uint32_t dst, const void* src) {
    asm volatile("cp.async.cg.shared.global [%0], [%1], 16;" :: "r"(dst), "l"(src));
}
__device__ __forceinline__ void mma_s8(int* c, const uint32_t* a, uint32_t b0, uint32_t b1) {
    asm volatile(
        "mma.sync.aligned.m16n8k32.row.col.s32.s8.s8.s32 "
        "{%0,%1,%2,%3}, {%4,%5,%6,%7}, {%8,%9}, {%0,%1,%2,%3};"
        : "+r"(c[0]), "+r"(c[1]), "+r"(c[2]), "+r"(c[3])
        : "r"(a[0]), "r"(a[1]), "r"(a[2]), "r"(a[3]), "r"(b0), "r"(b1));
}

// ---------------- input dtype detection ----------------
// Harness supports float32 / int32 / bfloat16; jnp.float16 inputs may arrive
// upcast to float32. Score 4096 leading elements of x under each
// interpretation; pick the one where values look like N(0,1) samples.
__device__ __forceinline__ int plausible(float v) {
    return (isfinite(v) && fabsf(v) <= 64.0f && (v == 0.0f || fabsf(v) >= 1e-4f)) ? 1 : 0;
}

__global__ void detect_dtype_kernel(const void* __restrict__ x) {
    __shared__ int cnt[3];
    const int tid = threadIdx.x;
    if (tid < 3) cnt[tid] = 0;
    __syncthreads();
    int c0 = 0, c1 = 0, c2 = 0;
    const __half* ph = (const __half*)x;
    const __nv_bfloat16* pb = (const __nv_bfloat16*)x;
    const float* pf = (const float*)x;
    #pragma unroll
    for (int i = 0; i < 16; ++i) {
        int idx = tid * 16 + i;
        c0 += plausible(__half2float(ph[idx]));
        c1 += plausible(__bfloat162float(pb[idx]));
        c2 += plausible(pf[idx]);
    }
    atomicAdd(&cnt[0], c0); atomicAdd(&cnt[1], c1); atomicAdd(&cnt[2], c2);
    __syncthreads();
    if (tid == 0) {
        int best = 0;
        if (cnt[1] > cnt[best]) best = 1;
        if (cnt[2] > cnt[best]) best = 2;
        g_dtype = best;
    }
}

// ---------------- quantization (bit-exact match to reference) ----------------
__device__ __forceinline__ void load16(const void* __restrict__ in, size_t row,
                                       int tid, int dt, float* __restrict__ f) {
    if (dt == 2) {
        const float4* rp = reinterpret_cast<const float4*>((const float*)in + row * K_DIM);
        #pragma unroll
        for (int i = 0; i < 4; ++i) {
            float4 v = rp[4 * tid + i];
            f[4 * i + 0] = v.x; f[4 * i + 1] = v.y; f[4 * i + 2] = v.z; f[4 * i + 3] = v.w;
        }
    } else if (dt == 0) {
        const uint4* rp = reinterpret_cast<const uint4*>((const __half*)in + row * K_DIM);
        uint4 va = rp[2 * tid], vb = rp[2 * tid + 1];
        uint32_t u[8] = {va.x, va.y, va.z, va.w, vb.x, vb.y, vb.z, vb.w};
        #pragma unroll
        for (int i = 0; i < 8; ++i) {
            float2 v = __half22float2(*reinterpret_cast<__half2*>(&u[i]));
            f[2 * i] = v.x; f[2 * i + 1] = v.y;
        }
    } else {
        const uint4* rp = reinterpret_cast<const uint4*>((const __nv_bfloat16*)in + row * K_DIM);
        uint4 va = rp[2 * tid], vb = rp[2 * tid + 1];
        uint32_t u[8] = {va.x, va.y, va.z, va.w, vb.x, vb.y, vb.z, vb.w};
        #pragma unroll
        for (int i = 0; i < 8; ++i) {
            __nv_bfloat162 b = *reinterpret_cast<__nv_bfloat162*>(&u[i]);
            f[2 * i] = __bfloat162float(b.x); f[2 * i + 1] = __bfloat162float(b.y);
        }
    }
}

__device__ __forceinline__ void quant_row(const void* __restrict__ in,
                                          int8_t* __restrict__ outq,
                                          float* __restrict__ scales) {
    const size_t row = blockIdx.x;
    const int tid = threadIdx.x;
    const int dt = g_dtype;

    float f[16];
    load16(in, row, tid, dt, f);

    float amax = 0.0f;
    #pragma unroll
    for (int i = 0; i < 16; ++i) amax = fmaxf(amax, fabsf(f[i]));
    #pragma unroll
    for (int o = 16; o > 0; o >>= 1)
        amax = fmaxf(amax, __shfl_xor_sync(0xffffffffu, amax, o));

    __shared__ float wmax[8];
    if ((tid & 31) == 0) wmax[tid >> 5] = amax;
    __syncthreads();
    float m = fmaxf(fmaxf(fmaxf(wmax[0], wmax[1]), fmaxf(wmax[2], wmax[3])),
                    fmaxf(fmaxf(wmax[4], wmax[5]), fmaxf(wmax[6], wmax[7])));
    // exact IEEE ops to match jnp: scale = max(absmax/7, 1e-8)
    const float scale = fmaxf(__fdiv_rn(m, 7.0f), 1e-8f);
    if (tid == 0) scales[row] = scale;

    int q[16];
    #pragma unroll
    for (int i = 0; i < 16; ++i)  // rintf = round-half-even = jnp.round
        q[i] = (int)fminf(7.0f, fmaxf(-8.0f, rintf(__fdiv_rn(f[i], scale))));

    uint32_t u[4];
    #pragma unroll
    for (int i = 0; i < 4; ++i)
        u[i] = (uint32_t)(q[4 * i] & 255) | ((uint32_t)(q[4 * i + 1] & 255) << 8) |
               ((uint32_t)(q[4 * i + 2] & 255) << 16) | ((uint32_t)(q[4 * i + 3] & 255) << 24);
    reinterpret_cast<uint4*>(outq + row * K_DIM)[tid] = make_uint4(u[0], u[1], u[2], u[3]);
}

__global__ void quant_x_kernel(const void* __restrict__ x) { quant_row(x, g_xq, g_xs); }
__global__ void quant_w_kernel(const void* __restrict__ w) { quant_row(w, g_wq, g_ws); }

// ---------------- GEMM (IMMA m16n8k32, 4-stage cp.async) ----------------
__device__ __forceinline__ void load_stage(uint32_t s_a, int tid,
                                           const int8_t* __restrict__ Ag,
                                           const int8_t* __restrict__ Bg) {
    const uint32_t s_b = s_a + A_BYTES;
    #pragma unroll
    for (int i = 0; i < 2; ++i) {   // 512 16B chunks / 256 threads
        int idx = tid + i * 256;
        int r = idx >> 2, c = idx & 3;
        cp16(s_a + (uint32_t)(r * ROW_PITCH + c * 16), Ag + (size_t)r * K_DIM + c * 16);
    }
    #pragma unroll
    for (int i = 0; i < 2; ++i) {
        int idx = tid + i * 256;
        int r = idx >> 2, c = idx & 3;
        cp16(s_b + (uint32_t)(r * ROW_PITCH + c * 16), Bg + (size_t)r * K_DIM + c * 16);
    }
    asm volatile("cp.async.commit_group;");
}

__global__ void __launch_bounds__(256, 2)
gemm_kernel(const float* __restrict__ bias, float* __restrict__ out) {
    extern __shared__ char smem[];
    const uint32_t sbase = smem_u32(smem);
    const int tid  = threadIdx.x;
    const int wid  = tid >> 5;
    const int lane = tid & 31;
    const int warp_m = wid >> 1;      // 0..3 -> 32-row tile
    const int warp_n = wid & 1;       // 0..1 -> 64-col tile
    const int m0 = blockIdx.y * BM;
    const int n0 = blockIdx.x * BN;

    const int8_t* Ag = g_xq + (size_t)m0 * K_DIM;
    const int8_t* Bg = g_wq + (size_t)n0 * K_DIM;

    // Direct fragment-load offsets from the PTX m16n8k32.s8 tables:
    // A: a0 row=lane>>2, kbyte=(lane&3)*4; a1 row+8; a2 kbyte+16; a3 both.
    // B: b0 n=lane>>2, kbyte=(lane&3)*4; b1 kbyte+16.
    const int gid = lane >> 2, tig = lane & 3;
    const uint32_t a_base = (uint32_t)((warp_m * 32 + gid) * ROW_PITCH + tig * 4);
    const uint32_t b_base = (uint32_t)(A_BYTES + (warp_n * 64 + gid) * ROW_PITCH + tig * 4);

    int acc[2][8][4];
    #pragma unroll
    for (int mf = 0; mf < 2; ++mf)
        #pragma unroll
        for (int nf = 0; nf < 8; ++nf)
            #pragma unroll
            for (int v = 0; v < 4; ++v) acc[mf][nf][v] = 0;

    // prologue: fill 3 stages
    #pragma unroll
    for (int s = 0; s < NSTAGES - 1; ++s)
        load_stage(sbase + s * STAGE_BYTES, tid, Ag + (size_t)s * BK, Bg + (size_t)s * BK);

    #pragma unroll 1
    for (int i = 0; i < KITERS; ++i) {
        if (i < KITERS - 2)       asm volatile("cp.async.wait_group 2;");
        else if (i == KITERS - 2) asm volatile("cp.async.wait_group 1;");
        else                      asm volatile("cp.async.wait_group 0;");
        __syncthreads();

        const char* st = smem + (size_t)((i & (NSTAGES - 1)) * STAGE_BYTES);
        #pragma unroll
        for (int ks = 0; ks < 2; ++ks) {
            const char* ak = st + a_base + ks * 32;
            const char* bk = st + b_base + ks * 32;
            uint32_t a[2][4];
            #pragma unroll
            for (int mf = 0; mf < 2; ++mf) {
                const char* ar = ak + mf * (16 * ROW_PITCH);
                a[mf][0] = *reinterpret_cast<const uint32_t*>(ar);
                a[mf][1] = *reinterpret_cast<const uint32_t*>(ar + 8 * ROW_PITCH);
                a[mf][2] = *reinterpret_cast<const uint32_t*>(ar + 16);
                a[mf][3] = *reinterpret_cast<const uint32_t*>(ar + 8 * ROW_PITCH + 16);
            }
            #pragma unroll
            for (int nf = 0; nf < 8; ++nf) {
                const char* br = bk + nf * (8 * ROW_PITCH);
                uint32_t b0 = *reinterpret_cast<const uint32_t*>(br);
                uint32_t b1 = *reinterpret_cast<const uint32_t*>(br + 16);
                #pragma unroll
                for (int mf = 0; mf < 2; ++mf)
                    mma_s8(acc[mf][nf], a[mf], b0, b1);
            }
        }

        const int nxt = i + NSTAGES - 1;
        if (nxt < KITERS)
            load_stage(sbase + (uint32_t)(nxt & (NSTAGES - 1)) * STAGE_BYTES, tid,
                       Ag + (size_t)nxt * BK, Bg + (size_t)nxt * BK);
    }

    // epilogue: match reference rounding exactly: ((acc*xs)*ws)+bias, no FMA
    #pragma unroll
    for (int mf = 0; mf < 2; ++mf) {
        const int r0 = m0 + warp_m * 32 + mf * 16 + gid;
        const float xs0 = g_xs[r0];
        const float xs1 = g_xs[r0 + 8];
        #pragma unroll
        for (int nf = 0; nf < 8; ++nf) {
            const int c = n0 + warp_n * 64 + nf * 8 + tig * 2;
            const float2 wsv = *reinterpret_cast<const float2*>(g_ws + c);
            const float2 bv  = *reinterpret_cast<const float2*>(bias + c);
            float2 o0, o1;
            o0.x = __fadd_rn(__fmul_rn(__fmul_rn((float)acc[mf][nf][0], xs0), wsv.x), bv.x);
            o0.y = __fadd_rn(__fmul_rn(__fmul_rn((float)acc[mf][nf][1], xs0), wsv.y), bv.y);
            o1.x = __fadd_rn(__fmul_rn(__fmul_rn((float)acc[mf][nf][2], xs1), wsv.x), bv.x);
            o1.y = __fadd_rn(__fmul_rn(__fmul_rn((float)acc[mf][nf][3], xs1), wsv.y), bv.y);
            *reinterpret_cast<float2*>(out + (size_t)r0 * N_DIM + c) = o0;
            *reinterpret_cast<float2*>(out + (size_t)(r0 + 8) * N_DIM + c) = o1;
        }
    }
}

// ---------------- launcher ----------------
extern "C" void kernel_launch(void* const* d_in, const int* in_sizes, int n_in,
                              void* d_out, int out_size) {
    (void)out_size;
    // robust input binding by element count
    const void* x = nullptr;
    const void* w = nullptr;
    const float* bias = nullptr;
    for (int i = 0; i < n_in; ++i) {
        if (in_sizes[i] == M_DIM * K_DIM)      x    = d_in[i];
        else if (in_sizes[i] == N_DIM * K_DIM) w    = d_in[i];
        else if (in_sizes[i] == N_DIM)         bias = (const float*)d_in[i];
    }
    float* out = (float*)d_out;

    cudaFuncSetAttribute(gemm_kernel, cudaFuncAttributeMaxDynamicSharedMemorySize, GEMM_SMEM);

    detect_dtype_kernel<<<1, 256>>>(x);
    quant_x_kernel<<<M_DIM, 256>>>(x);
    quant_w_kernel<<<N_DIM, 256>>>(w);
    gemm_kernel<<<dim3(N_DIM / BN, M_DIM / BM), 256, GEMM_SMEM>>>(bias, out);
}

// round 9
// speedup vs baseline: 2.1762x; 2.1762x over previous
#include <cuda_runtime.h>
#include <cuda_fp16.h>
#include <cuda_bf16.h>
#include <cstdint>
#include <cstddef>

#define M_DIM 16384
#define K_DIM 4096
#define N_DIM 4096

#define BM 128
#define BN 128
// BK in elements per stage = 32 bf16 = 64 bytes of K per row per stage
#define BK 32
#define KITERS (K_DIM / BK)   // 128
#define NSTAGES 4

// smem tile rows padded to 80 B: 16B-aligned, and (20*row + k4) mod 32 is a
// permutation over each fragment's warp access -> conflict-free LDS.32
#define ROW_PITCH 80
#define A_BYTES (BM * ROW_PITCH)                 // 10240
#define B_BYTES (BN * ROW_PITCH)                 // 10240
#define STAGE_BYTES (A_BYTES + B_BYTES)          // 20480
#define GEMM_SMEM (NSTAGES * STAGE_BYTES)        // 81920

static_assert(M_DIM % BM == 0 && N_DIM % BN == 0 && K_DIM % BK == 0, "tiling");

// Scratch (allocation-free rule: __device__ globals). bf16 quantized values.
__device__ __nv_bfloat16 g_xq[(size_t)M_DIM * K_DIM];   // 128 MB
__device__ __nv_bfloat16 g_wq[(size_t)N_DIM * K_DIM];   // 32 MB
__device__ float g_xs[M_DIM];
__device__ float g_ws[N_DIM];
__device__ int   g_dtype;                                // 0=f16, 1=bf16, 2=f32

// ---------------- PTX helpers ----------------
__device__ __forceinline__ uint32_t smem_u32(const void* p) {
    uint32_t a;
    asm("{ .reg .u64 t; cvta.to.shared.u64 t, %1; cvt.u32.u64 %0, t; }" : "=r"(a) : "l"(p));
    return a;
}
__device__ __forceinline__ void cp16(uint32_t dst, const void* src) {
    asm volatile("cp.async.cg.shared.global [%0], [%1], 16;" :: "r"(dst), "l"(src));
}
// bf16 MMA: m16n8k16, f32 accum. Fragment byte-offsets identical to s8 k32.
__device__ __forceinline__ void mma_bf16(float* c, const uint32_t* a, uint32_t b0, uint32_t b1) {
    asm volatile(
        "mma.sync.aligned.m16n8k16.row.col.f32.bf16.bf16.f32 "
        "{%0,%1,%2,%3}, {%4,%5,%6,%7}, {%8,%9}, {%0,%1,%2,%3};"
        : "+f"(c[0]), "+f"(c[1]), "+f"(c[2]), "+f"(c[3])
        : "r"(a[0]), "r"(a[1]), "r"(a[2]), "r"(a[3]), "r"(b0), "r"(b1));
}

// ---------------- input dtype detection ----------------
__device__ __forceinline__ int plausible(float v) {
    return (isfinite(v) && fabsf(v) <= 64.0f && (v == 0.0f || fabsf(v) >= 1e-4f)) ? 1 : 0;
}

__global__ void detect_dtype_kernel(const void* __restrict__ x) {
    __shared__ int cnt[3];
    const int tid = threadIdx.x;
    if (tid < 3) cnt[tid] = 0;
    __syncthreads();
    int c0 = 0, c1 = 0, c2 = 0;
    const __half* ph = (const __half*)x;
    const __nv_bfloat16* pb = (const __nv_bfloat16*)x;
    const float* pf = (const float*)x;
    #pragma unroll
    for (int i = 0; i < 16; ++i) {
        int idx = tid * 16 + i;
        c0 += plausible(__half2float(ph[idx]));
        c1 += plausible(__bfloat162float(pb[idx]));
        c2 += plausible(pf[idx]);
    }
    atomicAdd(&cnt[0], c0); atomicAdd(&cnt[1], c1); atomicAdd(&cnt[2], c2);
    __syncthreads();
    if (tid == 0) {
        int best = 0;
        if (cnt[1] > cnt[best]) best = 1;
        if (cnt[2] > cnt[best]) best = 2;
        g_dtype = best;
    }
}

// ---------------- quantization (bit-exact match to reference) ----------------
__device__ __forceinline__ void load16(const void* __restrict__ in, size_t row,
                                       int tid, int dt, float* __restrict__ f) {
    if (dt == 2) {
        const float4* rp = reinterpret_cast<const float4*>((const float*)in + row * K_DIM);
        #pragma unroll
        for (int i = 0; i < 4; ++i) {
            float4 v = rp[4 * tid + i];
            f[4 * i + 0] = v.x; f[4 * i + 1] = v.y; f[4 * i + 2] = v.z; f[4 * i + 3] = v.w;
        }
    } else if (dt == 0) {
        const uint4* rp = reinterpret_cast<const uint4*>((const __half*)in + row * K_DIM);
        uint4 va = rp[2 * tid], vb = rp[2 * tid + 1];
        uint32_t u[8] = {va.x, va.y, va.z, va.w, vb.x, vb.y, vb.z, vb.w};
        #pragma unroll
        for (int i = 0; i < 8; ++i) {
            float2 v = __half22float2(*reinterpret_cast<__half2*>(&u[i]));
            f[2 * i] = v.x; f[2 * i + 1] = v.y;
        }
    } else {
        const uint4* rp = reinterpret_cast<const uint4*>((const __nv_bfloat16*)in + row * K_DIM);
        uint4 va = rp[2 * tid], vb = rp[2 * tid + 1];
        uint32_t u[8] = {va.x, va.y, va.z, va.w, vb.x, vb.y, vb.z, vb.w};
        #pragma unroll
        for (int i = 0; i < 8; ++i) {
            __nv_bfloat162 b = *reinterpret_cast<__nv_bfloat162*>(&u[i]);
            f[2 * i] = __bfloat162float(b.x); f[2 * i + 1] = __bfloat162float(b.y);
        }
    }
}

__device__ __forceinline__ void quant_row(const void* __restrict__ in,
                                          __nv_bfloat16* __restrict__ outq,
                                          float* __restrict__ scales) {
    const size_t row = blockIdx.x;
    const int tid = threadIdx.x;
    const int dt = g_dtype;

    float f[16];
    load16(in, row, tid, dt, f);

    float amax = 0.0f;
    #pragma unroll
    for (int i = 0; i < 16; ++i) amax = fmaxf(amax, fabsf(f[i]));
    #pragma unroll
    for (int o = 16; o > 0; o >>= 1)
        amax = fmaxf(amax, __shfl_xor_sync(0xffffffffu, amax, o));

    __shared__ float wmax[8];
    if ((tid & 31) == 0) wmax[tid >> 5] = amax;
    __syncthreads();
    float m = fmaxf(fmaxf(fmaxf(wmax[0], wmax[1]), fmaxf(wmax[2], wmax[3])),
                    fmaxf(fmaxf(wmax[4], wmax[5]), fmaxf(wmax[6], wmax[7])));
    // exact IEEE ops to match jnp: scale = max(absmax/7, 1e-8)
    const float scale = fmaxf(__fdiv_rn(m, 7.0f), 1e-8f);
    if (tid == 0) scales[row] = scale;

    // quantized integers in [-8,7] -> exact bf16
    uint32_t u[8];
    #pragma unroll
    for (int i = 0; i < 8; ++i) {
        float qa = fminf(7.0f, fmaxf(-8.0f, rintf(__fdiv_rn(f[2 * i], scale))));
        float qb = fminf(7.0f, fmaxf(-8.0f, rintf(__fdiv_rn(f[2 * i + 1], scale))));
        __nv_bfloat162 b = __floats2bfloat162_rn(qa, qb);
        u[i] = *reinterpret_cast<uint32_t*>(&b);
    }
    uint4* qp = reinterpret_cast<uint4*>(outq + row * K_DIM);
    qp[2 * tid]     = make_uint4(u[0], u[1], u[2], u[3]);
    qp[2 * tid + 1] = make_uint4(u[4], u[5], u[6], u[7]);
}

__global__ void quant_x_kernel(const void* __restrict__ x) { quant_row(x, g_xq, g_xs); }
__global__ void quant_w_kernel(const void* __restrict__ w) { quant_row(w, g_wq, g_ws); }

// ---------------- GEMM (HMMA bf16 m16n8k16, 4-stage cp.async) ----------------
// Stage layout: per row 32 bf16 = 64 bytes (4 x 16B chunks), pitch 80 B.
__device__ __forceinline__ void load_stage(uint32_t s_a, int tid,
                                           const __nv_bfloat16* __restrict__ Ag,
                                           const __nv_bfloat16* __restrict__ Bg) {
    const uint32_t s_b = s_a + A_BYTES;
    #pragma unroll
    for (int i = 0; i < 2; ++i) {   // 512 16B chunks / 256 threads
        int idx = tid + i * 256;
        int r = idx >> 2, c = idx & 3;   // chunk c = 8 bf16 elements
        cp16(s_a + (uint32_t)(r * ROW_PITCH + c * 16), Ag + (size_t)r * K_DIM + c * 8);
    }
    #pragma unroll
    for (int i = 0; i < 2; ++i) {
        int idx = tid + i * 256;
        int r = idx >> 2, c = idx & 3;
        cp16(s_b + (uint32_t)(r * ROW_PITCH + c * 16), Bg + (size_t)r * K_DIM + c * 8);
    }
    asm volatile("cp.async.commit_group;");
}

__global__ void __launch_bounds__(256, 2)
gemm_kernel(const float* __restrict__ bias, float* __restrict__ out) {
    extern __shared__ char smem[];
    const uint32_t sbase = smem_u32(smem);
    const int tid  = threadIdx.x;
    const int wid  = tid >> 5;
    const int lane = tid & 31;
    const int warp_m = wid >> 1;      // 0..3 -> 32-row tile
    const int warp_n = wid & 1;       // 0..1 -> 64-col tile
    const int m0 = blockIdx.y * BM;
    const int n0 = blockIdx.x * BN;

    const __nv_bfloat16* Ag = g_xq + (size_t)m0 * K_DIM;
    const __nv_bfloat16* Bg = g_wq + (size_t)n0 * K_DIM;

    // bf16 m16n8k16 fragment offsets (bytes — identical geometry to s8 k32):
    // A: a0 row=gid, kbyte=tig*4; a1 row+8; a2 kbyte+16; a3 both.
    // B: b0 n=gid, kbyte=tig*4; b1 kbyte+16.
    const int gid = lane >> 2, tig = lane & 3;
    const uint32_t a_base = (uint32_t)((warp_m * 32 + gid) * ROW_PITCH + tig * 4);
    const uint32_t b_base = (uint32_t)(A_BYTES + (warp_n * 64 + gid) * ROW_PITCH + tig * 4);

    float acc[2][8][4];
    #pragma unroll
    for (int mf = 0; mf < 2; ++mf)
        #pragma unroll
        for (int nf = 0; nf < 8; ++nf)
            #pragma unroll
            for (int v = 0; v < 4; ++v) acc[mf][nf][v] = 0.0f;

    // prologue: fill 3 stages
    #pragma unroll
    for (int s = 0; s < NSTAGES - 1; ++s)
        load_stage(sbase + s * STAGE_BYTES, tid, Ag + (size_t)s * BK, Bg + (size_t)s * BK);

    #pragma unroll 1
    for (int i = 0; i < KITERS; ++i) {
        if (i < KITERS - 2)       asm volatile("cp.async.wait_group 2;");
        else if (i == KITERS - 2) asm volatile("cp.async.wait_group 1;");
        else                      asm volatile("cp.async.wait_group 0;");
        __syncthreads();

        const char* st = smem + (size_t)((i & (NSTAGES - 1)) * STAGE_BYTES);
        #pragma unroll
        for (int ks = 0; ks < 2; ++ks) {      // ks covers 16 elems = 32 bytes
            const char* ak = st + a_base + ks * 32;
            const char* bk = st + b_base + ks * 32;
            uint32_t a[2][4];
            #pragma unroll
            for (int mf = 0; mf < 2; ++mf) {
                const char* ar = ak + mf * (16 * ROW_PITCH);
                a[mf][0] = *reinterpret_cast<const uint32_t*>(ar);
                a[mf][1] = *reinterpret_cast<const uint32_t*>(ar + 8 * ROW_PITCH);
                a[mf][2] = *reinterpret_cast<const uint32_t*>(ar + 16);
                a[mf][3] = *reinterpret_cast<const uint32_t*>(ar + 8 * ROW_PITCH + 16);
            }
            #pragma unroll
            for (int nf = 0; nf < 8; ++nf) {
                const char* br = bk + nf * (8 * ROW_PITCH);
                uint32_t b0 = *reinterpret_cast<const uint32_t*>(br);
                uint32_t b1 = *reinterpret_cast<const uint32_t*>(br + 16);
                #pragma unroll
                for (int mf = 0; mf < 2; ++mf)
                    mma_bf16(acc[mf][nf], a[mf], b0, b1);
            }
        }

        const int nxt = i + NSTAGES - 1;
        if (nxt < KITERS)
            load_stage(sbase + (uint32_t)(nxt & (NSTAGES - 1)) * STAGE_BYTES, tid,
                       Ag + (size_t)nxt * BK, Bg + (size_t)nxt * BK);
    }

    // epilogue: acc holds the exact integer dot product as f32.
    // match reference rounding exactly: ((acc*xs)*ws)+bias, no FMA contraction
    #pragma unroll
    for (int mf = 0; mf < 2; ++mf) {
        const int r0 = m0 + warp_m * 32 + mf * 16 + gid;
        const float xs0 = g_xs[r0];
        const float xs1 = g_xs[r0 + 8];
        #pragma unroll
        for (int nf = 0; nf < 8; ++nf) {
            const int c = n0 + warp_n * 64 + nf * 8 + tig * 2;
            const float2 wsv = *reinterpret_cast<const float2*>(g_ws + c);
            const float2 bv  = *reinterpret_cast<const float2*>(bias + c);
            float2 o0, o1;
            o0.x = __fadd_rn(__fmul_rn(__fmul_rn(acc[mf][nf][0], xs0), wsv.x), bv.x);
            o0.y = __fadd_rn(__fmul_rn(__fmul_rn(acc[mf][nf][1], xs0), wsv.y), bv.y);
            o1.x = __fadd_rn(__fmul_rn(__fmul_rn(acc[mf][nf][2], xs1), wsv.x), bv.x);
            o1.y = __fadd_rn(__fmul_rn(__fmul_rn(acc[mf][nf][3], xs1), wsv.y), bv.y);
            *reinterpret_cast<float2*>(out + (size_t)r0 * N_DIM + c) = o0;
            *reinterpret_cast<float2*>(out + (size_t)(r0 + 8) * N_DIM + c) = o1;
        }
    }
}

// ---------------- launcher ----------------
extern "C" void kernel_launch(void* const* d_in, const int* in_sizes, int n_in,
                              void* d_out, int out_size) {
    (void)out_size;
    const void* x = nullptr;
    const void* w = nullptr;
    const float* bias = nullptr;
    for (int i = 0; i < n_in; ++i) {
        if (in_sizes[i] == M_DIM * K_DIM)      x    = d_in[i];
        else if (in_sizes[i] == N_DIM * K_DIM) w    = d_in[i];
        else if (in_sizes[i] == N_DIM)         bias = (const float*)d_in[i];
    }
    float* out = (float*)d_out;

    cudaFuncSetAttribute(gemm_kernel, cudaFuncAttributeMaxDynamicSharedMemorySize, GEMM_SMEM);

    detect_dtype_kernel<<<1, 256>>>(x);
    quant_x_kernel<<<M_DIM, 256>>>(x);
    quant_w_kernel<<<N_DIM, 256>>>(w);
    gemm_kernel<<<dim3(N_DIM / BN, M_DIM / BM), 256, GEMM_SMEM>>>(bias, out);
}

// round 12
// speedup vs baseline: 2.4071x; 1.1061x over previous
#include <cuda_runtime.h>
#include <cuda_fp16.h>
#include <cuda_bf16.h>
#include <cstdint>
#include <cstddef>

#define M_DIM 16384
#define K_DIM 4096
#define N_DIM 4096

#define BM 128
#define BN 128
// BK in elements per stage = 32 bf16 = 64 bytes of K per row per stage
#define BK 32
#define KITERS (K_DIM / BK)   // 128
#define NSTAGES 4

// smem tile rows padded to 80 B: 16B-aligned; for 8-row x 16B ldmatrix phases
// bank offsets (20*r mod 32) = {0,20,8,28,16,4,24,12}, each +0..3 -> all 32
// banks exactly once -> conflict-free LDSM.
#define ROW_PITCH 80
#define A_BYTES (BM * ROW_PITCH)                 // 10240
#define B_BYTES (BN * ROW_PITCH)                 // 10240
#define STAGE_BYTES (A_BYTES + B_BYTES)          // 20480
#define GEMM_SMEM (NSTAGES * STAGE_BYTES)        // 81920

static_assert(M_DIM % BM == 0 && N_DIM % BN == 0 && K_DIM % BK == 0, "tiling");

// Scratch (allocation-free rule: __device__ globals). bf16 quantized values.
__device__ __nv_bfloat16 g_xq[(size_t)M_DIM * K_DIM];   // 128 MB
__device__ __nv_bfloat16 g_wq[(size_t)N_DIM * K_DIM];   // 32 MB
__device__ float g_xs[M_DIM];
__device__ float g_ws[N_DIM];
__device__ int   g_dtype;                                // 0=f16, 1=bf16, 2=f32

// ---------------- PTX helpers ----------------
__device__ __forceinline__ uint32_t smem_u32(const void* p) {
    uint32_t a;
    asm("{ .reg .u64 t; cvta.to.shared.u64 t, %1; cvt.u32.u64 %0, t; }" : "=r"(a) : "l"(p));
    return a;
}
__device__ __forceinline__ void cp16(uint32_t dst, const void* src) {
    asm volatile("cp.async.cg.shared.global [%0], [%1], 16;" :: "r"(dst), "l"(src));
}
__device__ __forceinline__ void ldsm_x4(uint32_t* r, uint32_t addr) {
    asm volatile("ldmatrix.sync.aligned.m8n8.x4.shared.b16 {%0,%1,%2,%3}, [%4];"
                 : "=r"(r[0]), "=r"(r[1]), "=r"(r[2]), "=r"(r[3]) : "r"(addr));
}
// bf16 MMA: m16n8k16, f32 accum.
__device__ __forceinline__ void mma_bf16(float* c, const uint32_t* a, uint32_t b0, uint32_t b1) {
    asm volatile(
        "mma.sync.aligned.m16n8k16.row.col.f32.bf16.bf16.f32 "
        "{%0,%1,%2,%3}, {%4,%5,%6,%7}, {%8,%9}, {%0,%1,%2,%3};"
        : "+f"(c[0]), "+f"(c[1]), "+f"(c[2]), "+f"(c[3])
        : "r"(a[0]), "r"(a[1]), "r"(a[2]), "r"(a[3]), "r"(b0), "r"(b1));
}

// ---------------- input dtype detection ----------------
__device__ __forceinline__ int plausible(float v) {
    return (isfinite(v) && fabsf(v) <= 64.0f && (v == 0.0f || fabsf(v) >= 1e-4f)) ? 1 : 0;
}

__global__ void detect_dtype_kernel(const void* __restrict__ x) {
    __shared__ int cnt[3];
    const int tid = threadIdx.x;
    if (tid < 3) cnt[tid] = 0;
    __syncthreads();
    int c0 = 0, c1 = 0, c2 = 0;
    const __half* ph = (const __half*)x;
    const __nv_bfloat16* pb = (const __nv_bfloat16*)x;
    const float* pf = (const float*)x;
    #pragma unroll
    for (int i = 0; i < 16; ++i) {
        int idx = tid * 16 + i;
        c0 += plausible(__half2float(ph[idx]));
        c1 += plausible(__bfloat162float(pb[idx]));
        c2 += plausible(pf[idx]);
    }
    atomicAdd(&cnt[0], c0); atomicAdd(&cnt[1], c1); atomicAdd(&cnt[2], c2);
    __syncthreads();
    if (tid == 0) {
        int best = 0;
        if (cnt[1] > cnt[best]) best = 1;
        if (cnt[2] > cnt[best]) best = 2;
        g_dtype = best;
    }
}

// ---------------- quantization (bit-exact match to reference) ----------------
__device__ __forceinline__ void load16(const void* __restrict__ in, size_t row,
                                       int tid, int dt, float* __restrict__ f) {
    if (dt == 2) {
        const float4* rp = reinterpret_cast<const float4*>((const float*)in + row * K_DIM);
        #pragma unroll
        for (int i = 0; i < 4; ++i) {
            float4 v = rp[4 * tid + i];
            f[4 * i + 0] = v.x; f[4 * i + 1] = v.y; f[4 * i + 2] = v.z; f[4 * i + 3] = v.w;
        }
    } else if (dt == 0) {
        const uint4* rp = reinterpret_cast<const uint4*>((const __half*)in + row * K_DIM);
        uint4 va = rp[2 * tid], vb = rp[2 * tid + 1];
        uint32_t u[8] = {va.x, va.y, va.z, va.w, vb.x, vb.y, vb.z, vb.w};
        #pragma unroll
        for (int i = 0; i < 8; ++i) {
            float2 v = __half22float2(*reinterpret_cast<__half2*>(&u[i]));
            f[2 * i] = v.x; f[2 * i + 1] = v.y;
        }
    } else {
        const uint4* rp = reinterpret_cast<const uint4*>((const __nv_bfloat16*)in + row * K_DIM);
        uint4 va = rp[2 * tid], vb = rp[2 * tid + 1];
        uint32_t u[8] = {va.x, va.y, va.z, va.w, vb.x, vb.y, vb.z, vb.w};
        #pragma unroll
        for (int i = 0; i < 8; ++i) {
            __nv_bfloat162 b = *reinterpret_cast<__nv_bfloat162*>(&u[i]);
            f[2 * i] = __bfloat162float(b.x); f[2 * i + 1] = __bfloat162float(b.y);
        }
    }
}

__device__ __forceinline__ void quant_row(const void* __restrict__ in,
                                          __nv_bfloat16* __restrict__ outq,
                                          float* __restrict__ scales) {
    const size_t row = blockIdx.x;
    const int tid = threadIdx.x;
    const int dt = g_dtype;

    float f[16];
    load16(in, row, tid, dt, f);

    float amax = 0.0f;
    #pragma unroll
    for (int i = 0; i < 16; ++i) amax = fmaxf(amax, fabsf(f[i]));
    #pragma unroll
    for (int o = 16; o > 0; o >>= 1)
        amax = fmaxf(amax, __shfl_xor_sync(0xffffffffu, amax, o));

    __shared__ float wmax[8];
    if ((tid & 31) == 0) wmax[tid >> 5] = amax;
    __syncthreads();
    float m = fmaxf(fmaxf(fmaxf(wmax[0], wmax[1]), fmaxf(wmax[2], wmax[3])),
                    fmaxf(fmaxf(wmax[4], wmax[5]), fmaxf(wmax[6], wmax[7])));
    // exact IEEE ops to match jnp: scale = max(absmax/7, 1e-8)
    const float scale = fmaxf(__fdiv_rn(m, 7.0f), 1e-8f);
    if (tid == 0) scales[row] = scale;

    // quantized integers in [-8,7] -> exact bf16
    uint32_t u[8];
    #pragma unroll
    for (int i = 0; i < 8; ++i) {
        float qa = fminf(7.0f, fmaxf(-8.0f, rintf(__fdiv_rn(f[2 * i], scale))));
        float qb = fminf(7.0f, fmaxf(-8.0f, rintf(__fdiv_rn(f[2 * i + 1], scale))));
        __nv_bfloat162 b = __floats2bfloat162_rn(qa, qb);
        u[i] = *reinterpret_cast<uint32_t*>(&b);
    }
    uint4* qp = reinterpret_cast<uint4*>(outq + row * K_DIM);
    qp[2 * tid]     = make_uint4(u[0], u[1], u[2], u[3]);
    qp[2 * tid + 1] = make_uint4(u[4], u[5], u[6], u[7]);
}

__global__ void quant_x_kernel(const void* __restrict__ x) { quant_row(x, g_xq, g_xs); }
__global__ void quant_w_kernel(const void* __restrict__ w) { quant_row(w, g_wq, g_ws); }

// ---------------- GEMM (HMMA bf16 m16n8k16, ldmatrix feed, 4-stage) ----------
// Stage layout: per row 32 bf16 = 64 bytes (4 x 16B chunks), pitch 80 B.
__device__ __forceinline__ void load_stage(uint32_t s_a, int tid,
                                           const __nv_bfloat16* __restrict__ Ag,
                                           const __nv_bfloat16* __restrict__ Bg) {
    const uint32_t s_b = s_a + A_BYTES;
    #pragma unroll
    for (int i = 0; i < 2; ++i) {   // 512 16B chunks / 256 threads
        int idx = tid + i * 256;
        int r = idx >> 2, c = idx & 3;   // chunk c = 8 bf16 elements
        cp16(s_a + (uint32_t)(r * ROW_PITCH + c * 16), Ag + (size_t)r * K_DIM + c * 8);
    }
    #pragma unroll
    for (int i = 0; i < 2; ++i) {
        int idx = tid + i * 256;
        int r = idx >> 2, c = idx & 3;
        cp16(s_b + (uint32_t)(r * ROW_PITCH + c * 16), Bg + (size_t)r * K_DIM + c * 8);
    }
    asm volatile("cp.async.commit_group;");
}

__global__ void __launch_bounds__(256, 2)
gemm_kernel(const float* __restrict__ bias, float* __restrict__ out) {
    extern __shared__ char smem[];
    const uint32_t sbase = smem_u32(smem);
    const int tid  = threadIdx.x;
    const int wid  = tid >> 5;
    const int lane = tid & 31;
    const int warp_m = wid >> 1;      // 0..3 -> 32-row tile
    const int warp_n = wid & 1;       // 0..1 -> 64-col tile
    const int m0 = blockIdx.y * BM;
    const int n0 = blockIdx.x * BN;

    const __nv_bfloat16* Ag = g_xq + (size_t)m0 * K_DIM;
    const __nv_bfloat16* Bg = g_wq + (size_t)n0 * K_DIM;

    // ldmatrix x4 addresses (byte offsets within stage):
    // A (m16 x k16 tile mf, halves ks): matrices ordered
    //   (rows0-7,k0-7)(rows8-15,k0-7)(rows0-7,k8-15)(rows8-15,k8-15)
    //   lane -> row (lane&15), kbyte (lane>>4)*16  => regs r0..r3 = a0..a3
    uint32_t aoff[2];
    #pragma unroll
    for (int mf = 0; mf < 2; ++mf)
        aoff[mf] = (uint32_t)((warp_m * 32 + mf * 16 + (lane & 15)) * ROW_PITCH
                              + (lane >> 4) * 16);
    // B (two n8 tiles per x4): matrices (nA,k0-7)(nA,k8-15)(nB,k0-7)(nB,k8-15)
    //   lane -> n = nf2*16 + ((lane>>4)&1)*8 + (lane&7), kbyte ((lane>>3)&1)*16
    //   => r0,r1 = b0,b1 of tile nA ; r2,r3 = b0,b1 of tile nB
    uint32_t boff[4];
    #pragma unroll
    for (int nf2 = 0; nf2 < 4; ++nf2)
        boff[nf2] = (uint32_t)(A_BYTES
                               + (warp_n * 64 + nf2 * 16 + ((lane >> 4) & 1) * 8 + (lane & 7))
                                 * ROW_PITCH
                               + ((lane >> 3) & 1) * 16);

    float acc[2][8][4];
    #pragma unroll
    for (int mf = 0; mf < 2; ++mf)
        #pragma unroll
        for (int nf = 0; nf < 8; ++nf)
            #pragma unroll
            for (int v = 0; v < 4; ++v) acc[mf][nf][v] = 0.0f;

    // prologue: fill 3 stages
    #pragma unroll
    for (int s = 0; s < NSTAGES - 1; ++s)
        load_stage(sbase + s * STAGE_BYTES, tid, Ag + (size_t)s * BK, Bg + (size_t)s * BK);

    #pragma unroll 1
    for (int i = 0; i < KITERS; ++i) {
        if (i < KITERS - 2)       asm volatile("cp.async.wait_group 2;");
        else if (i == KITERS - 2) asm volatile("cp.async.wait_group 1;");
        else                      asm volatile("cp.async.wait_group 0;");
        __syncthreads();

        const uint32_t st = sbase + (uint32_t)((i & (NSTAGES - 1)) * STAGE_BYTES);
        #pragma unroll
        for (int ks = 0; ks < 2; ++ks) {      // ks covers 16 elems = 32 bytes
            uint32_t a[2][4], b[4][4];
            #pragma unroll
            for (int mf = 0; mf < 2; ++mf) ldsm_x4(a[mf], st + aoff[mf] + ks * 32);
            #pragma unroll
            for (int nf2 = 0; nf2 < 4; ++nf2) ldsm_x4(b[nf2], st + boff[nf2] + ks * 32);
            #pragma unroll
            for (int nf = 0; nf < 8; ++nf) {
                const uint32_t b0 = b[nf >> 1][(nf & 1) * 2];
                const uint32_t b1 = b[nf >> 1][(nf & 1) * 2 + 1];
                #pragma unroll
                for (int mf = 0; mf < 2; ++mf)
                    mma_bf16(acc[mf][nf], a[mf], b0, b1);
            }
        }

        const int nxt = i + NSTAGES - 1;
        if (nxt < KITERS)
            load_stage(sbase + (uint32_t)(nxt & (NSTAGES - 1)) * STAGE_BYTES, tid,
                       Ag + (size_t)nxt * BK, Bg + (size_t)nxt * BK);
    }

    // epilogue: acc holds the exact integer dot product as f32.
    // match reference rounding exactly: ((acc*xs)*ws)+bias, no FMA contraction
    const int gid = lane >> 2, tig = lane & 3;
    #pragma unroll
    for (int mf = 0; mf < 2; ++mf) {
        const int r0 = m0 + warp_m * 32 + mf * 16 + gid;
        const float xs0 = g_xs[r0];
        const float xs1 = g_xs[r0 + 8];
        #pragma unroll
        for (int nf = 0; nf < 8; ++nf) {
            const int c = n0 + warp_n * 64 + nf * 8 + tig * 2;
            const float2 wsv = *reinterpret_cast<const float2*>(g_ws + c);
            const float2 bv  = *reinterpret_cast<const float2*>(bias + c);
            float2 o0, o1;
            o0.x = __fadd_rn(__fmul_rn(__fmul_rn(acc[mf][nf][0], xs0), wsv.x), bv.x);
            o0.y = __fadd_rn(__fmul_rn(__fmul_rn(acc[mf][nf][1], xs0), wsv.y), bv.y);
            o1.x = __fadd_rn(__fmul_rn(__fmul_rn(acc[mf][nf][2], xs1), wsv.x), bv.x);
            o1.y = __fadd_rn(__fmul_rn(__fmul_rn(acc[mf][nf][3], xs1), wsv.y), bv.y);
            *reinterpret_cast<float2*>(out + (size_t)r0 * N_DIM + c) = o0;
            *reinterpret_cast<float2*>(out + (size_t)(r0 + 8) * N_DIM + c) = o1;
        }
    }
}

// ---------------- launcher ----------------
extern "C" void kernel_launch(void* const* d_in, const int* in_sizes, int n_in,
                              void* d_out, int out_size) {
    (void)out_size;
    const void* x = nullptr;
    const void* w = nullptr;
    const float* bias = nullptr;
    for (int i = 0; i < n_in; ++i) {
        if (in_sizes[i] == M_DIM * K_DIM)      x    = d_in[i];
        else if (in_sizes[i] == N_DIM * K_DIM) w    = d_in[i];
        else if (in_sizes[i] == N_DIM)         bias = (const float*)d_in[i];
    }
    float* out = (float*)d_out;

    cudaFuncSetAttribute(gemm_kernel, cudaFuncAttributeMaxDynamicSharedMemorySize, GEMM_SMEM);

    detect_dtype_kernel<<<1, 256>>>(x);
    quant_x_kernel<<<M_DIM, 256>>>(x);
    quant_w_kernel<<<N_DIM, 256>>>(w);
    gemm_kernel<<<dim3(N_DIM / BN, M_DIM / BM), 256, GEMM_SMEM>>>(bias, out);
}